// round 5
// baseline (speedup 1.0000x reference)
#include <cuda_runtime.h>
#include <math.h>

// Problem constants
#define B_    64
#define L_    512
#define C_    1024
#define NT    7
#define START_ 5
#define STOP_  6
#define NROWS (B_ * L_)   // 32768
#define NPAIRS (NROWS / 2)

__device__ float g_nll[B_];

// packed f32x2 FMA (Blackwell; PTX-only form -> single FFMA2)
__device__ __forceinline__ void ffma2(unsigned long long& d,
                                      unsigned long long a,
                                      unsigned long long b) {
    asm("fma.rn.f32x2 %0, %1, %2, %0;" : "+l"(d) : "l"(a), "l"(b));
}
// 128-bit streaming global load into two 64-bit (f32x2) regs
__device__ __forceinline__ void ldg_cs_v2b64(const void* p,
                                             unsigned long long& lo,
                                             unsigned long long& hi) {
    asm("ld.global.cs.v2.b64 {%0, %1}, [%2];" : "=l"(lo), "=l"(hi) : "l"(p));
}
// 128-bit shared load into two 64-bit (f32x2) regs  -> LDS.128, conflict-free
__device__ __forceinline__ void lds_v2b64(unsigned smem_addr,
                                          unsigned long long& lo,
                                          unsigned long long& hi) {
    asm("ld.shared.v2.b64 {%0, %1}, [%2];" : "=l"(lo), "=l"(hi) : "r"(smem_addr));
}
__device__ __forceinline__ float unpack_sum(unsigned long long v) {
    union { unsigned long long u; float2 f; } cv; cv.u = v;
    return cv.f.x + cv.f.y;
}
__device__ __forceinline__ unsigned smem_u32(const void* p) {
    unsigned a;
    asm("{ .reg .u64 t; cvta.to.shared.u64 t, %1; cvt.u32.u64 %0, t; }"
        : "=r"(a) : "l"(p));
    return a;
}

// ---------------------------------------------------------------------------
// Kernel 1: pred = X @ W^T + b.  Warp per TWO rows, f32x2 packed FMAs,
// W in shared read via conflict-free LDS.128, 128-reg budget, persistent grid.
// ---------------------------------------------------------------------------
__global__ void __launch_bounds__(256, 2) k1_gemm(
    const float* __restrict__ X, const int* __restrict__ labels,
    const float* __restrict__ W, const float* __restrict__ bias,
    float* __restrict__ out)
{
    __shared__ __align__(16) unsigned long long sW[NT][C_ / 2]; // f32x2 pairs
    __shared__ float sb[8];
    for (int i = threadIdx.x; i < NT * (C_ / 2); i += 256)
        sW[i / (C_ / 2)][i % (C_ / 2)] = ((const unsigned long long*)W)[i];
    if (threadIdx.x < NT) sb[threadIdx.x] = bias[threadIdx.x];
    __syncthreads();

    const int lane  = threadIdx.x & 31;
    const int gwarp = (blockIdx.x * blockDim.x + threadIdx.x) >> 5;
    const int nwarp = (gridDim.x * blockDim.x) >> 5;
    float* pred = out + 1 + NROWS;

    const unsigned sW_base = smem_u32(&sW[0][0]);

    for (int pair = gwarp; pair < NPAIRS; pair += nwarp) {
        const int row0 = pair * 2;
        const int row1 = row0 + 1;
        const float* x0 = X + (size_t)row0 * C_;
        const float* x1 = X + (size_t)row1 * C_;

        // Prefetch: 16 x LDG.128 (8 per row) => 8KB in flight per warp.
        unsigned long long a_lo[8], a_hi[8], b_lo[8], b_hi[8];
        #pragma unroll
        for (int k = 0; k < 8; k++) {
            const int idx = (lane + 32 * k) * 4;
            ldg_cs_v2b64(x0 + idx, a_lo[k], a_hi[k]);
            ldg_cs_v2b64(x1 + idx, b_lo[k], b_hi[k]);
        }

        unsigned long long acc0[NT], acc1[NT];
        #pragma unroll
        for (int t = 0; t < NT; t++) { acc0[t] = 0ull; acc1[t] = 0ull; }

        #pragma unroll
        for (int k = 0; k < 8; k++) {
            // 16-byte offset per lane -> LDS.128 conflict-free
            const unsigned off = (unsigned)(lane + 32 * k) * 16u;
            #pragma unroll
            for (int t = 0; t < NT; t++) {
                unsigned long long wlo, whi;
                lds_v2b64(sW_base + (unsigned)t * (C_ / 2) * 8u + off, wlo, whi);
                ffma2(acc0[t], a_lo[k], wlo);
                ffma2(acc0[t], a_hi[k], whi);
                ffma2(acc1[t], b_lo[k], wlo);
                ffma2(acc1[t], b_hi[k], whi);
            }
        }

        float r0[NT], r1[NT];
        #pragma unroll
        for (int t = 0; t < NT; t++) {
            r0[t] = unpack_sum(acc0[t]);
            r1[t] = unpack_sum(acc1[t]);
            #pragma unroll
            for (int o = 16; o > 0; o >>= 1) {
                r0[t] += __shfl_xor_sync(0xffffffffu, r0[t], o);
                r1[t] += __shfl_xor_sync(0xffffffffu, r1[t], o);
            }
        }

        float v0 = 0.f, v1 = 0.f;
        #pragma unroll
        for (int t = 0; t < NT; t++) {
            if (lane == t)     v0 = r0[t];
            if (lane == t + 8) v1 = r1[t];
        }
        if (lane < NT) {
            pred[(size_t)row0 * NT + lane] = v0 + sb[lane];
        } else if (lane >= 8 && lane < 8 + NT) {
            pred[(size_t)row1 * NT + (lane - 8)] = v1 + sb[lane - 8];
        } else if (lane == 16) {
            out[1 + row0] = (float)labels[row0];
        } else if (lane == 17) {
            out[1 + row1] = (float)labels[row1];
        }
    }
}

// ---------------------------------------------------------------------------
// Kernel 2: CRF forward in exp-domain (chunked matrix products) + gold score.
// One block per batch element; 128 threads = 16 chunks x 8 columns.
// ---------------------------------------------------------------------------
__global__ void __launch_bounds__(128) k2_crf(
    const float* __restrict__ trans,
    const int* __restrict__ labels,
    const float* __restrict__ outbuf)
{
    __shared__ float sEE[L_ * 8];       // 16 KB: exp-emissions for this batch
    __shared__ float sET[8][8];         // exp(transitions), padded
    __shared__ float sT[49];            // raw transitions
    __shared__ float sM[16][8][8];      // chunk matrices: [chunk][col][row]
    __shared__ float sS[16];            // chunk log-scales
    __shared__ float sv[8];
    __shared__ float sgold, svscale;

    const int b   = blockIdx.x;
    const int tid = threadIdx.x;
    const float* pred = outbuf + 1 + NROWS;

    {   // exp(emissions) for this batch, padded [L][8] (col 7 = 0)
        const float* pb = pred + (size_t)b * L_ * NT;
        for (int i = tid; i < L_ * NT; i += 128) {
            int r = i / NT, c = i % NT;
            sEE[r * 8 + c] = expf(pb[i]);
        }
        for (int r = tid; r < L_; r += 128) sEE[r * 8 + 7] = 0.f;
    }
    if (tid < 64) {
        int n = tid >> 3, p = tid & 7;
        sET[n][p] = (n < NT && p < NT) ? expf(trans[n * NT + p]) : 0.f;
    }
    if (tid < 49) sT[tid] = trans[tid];
    __syncthreads();

    // ---- Stage A: per-chunk matrix product (thread per column) ----
    {
        const int chunk = tid >> 3;     // 0..15
        const int col   = tid & 7;      // 0..7 (7 = zero pad column)
        float ET[NT][NT];
        #pragma unroll
        for (int n = 0; n < NT; n++)
            #pragma unroll
            for (int p = 0; p < NT; p++) ET[n][p] = sET[n][p];

        const int t0 = chunk * 32;
        float u[NT];
        #pragma unroll
        for (int n = 0; n < NT; n++)
            u[n] = (col < NT) ? sET[n][col] * sEE[t0 * 8 + n] : 0.f;
        float s = 0.f;

        for (int step = 1; step < 32; step++) {
            const float* ee = &sEE[(t0 + step) * 8];
            float v[NT];
            #pragma unroll
            for (int n = 0; n < NT; n++) {
                float a = ET[n][0] * u[0];
                #pragma unroll
                for (int p = 1; p < NT; p++) a = fmaf(ET[n][p], u[p], a);
                v[n] = a * ee[n];
            }
            #pragma unroll
            for (int n = 0; n < NT; n++) u[n] = v[n];

            if ((step & 7) == 7) {      // renormalize (shared scale per chunk)
                float m = u[0];
                #pragma unroll
                for (int n = 1; n < NT; n++) m = fmaxf(m, u[n]);
                m = fmaxf(m, __shfl_xor_sync(0xffffffffu, m, 1));
                m = fmaxf(m, __shfl_xor_sync(0xffffffffu, m, 2));
                m = fmaxf(m, __shfl_xor_sync(0xffffffffu, m, 4));
                if (m > 0.f) {
                    float inv = 1.f / m;
                    #pragma unroll
                    for (int n = 0; n < NT; n++) u[n] *= inv;
                    s += logf(m);
                }
            }
        }
        #pragma unroll
        for (int n = 0; n < NT; n++) sM[chunk][col][n] = u[n];
        sM[chunk][col][7] = 0.f;
        if (col == 0) sS[chunk] = s;
    }
    __syncthreads();

    // ---- Stage B: sequential matrix-vector combine (warp 0, lanes 0..7),
    //      gold score in parallel on warp 1 ----
    if (tid < 8) {
        const int n = tid;
        float v     = sM[0][START_][n];   // init vector = e_START
        float scale = sS[0];
        for (int c = 1; c < 16; c++) {
            sv[n] = v;
            __syncwarp(0x000000ffu);
            float a = 0.f;
            #pragma unroll
            for (int j = 0; j < NT; j++) a = fmaf(sM[c][j][n], sv[j], a);
            float m = a;
            m = fmaxf(m, __shfl_xor_sync(0xffu, m, 1));
            m = fmaxf(m, __shfl_xor_sync(0xffu, m, 2));
            m = fmaxf(m, __shfl_xor_sync(0xffu, m, 4));
            if (m > 0.f) { v = a / m; scale += logf(m); }
            else         { v = a; }
            scale += sS[c];
            __syncwarp(0x000000ffu);
        }
        sv[n] = v;
        if (n == 0) svscale = scale;
    } else if (tid >= 32 && tid < 64) {
        const int lane = tid - 32;
        const int base = b * L_;
        float acc = 0.f;
        #pragma unroll 4
        for (int k = 0; k < 16; k++) {
            int t   = lane + k * 32;
            int tag = labels[base + t];
            int pt  = (t == 0) ? START_ : labels[base + t - 1];
            acc += pred[(size_t)(base + t) * NT + tag] + sT[tag * NT + pt];
        }
        #pragma unroll
        for (int o = 16; o > 0; o >>= 1)
            acc += __shfl_xor_sync(0xffffffffu, acc, o);
        if (lane == 0) sgold = acc + sT[STOP_ * NT + labels[base + L_ - 1]];
    }
    __syncthreads();

    if (tid == 0) {
        float sum = 0.f;
        #pragma unroll
        for (int n = 0; n < NT; n++) sum += sv[n] * sET[STOP_][n];
        g_nll[b] = logf(sum) + svscale - sgold;
    }
}

// ---------------------------------------------------------------------------
// Kernel 3: deterministic sum of 64 per-batch NLLs -> d_out[0]
// ---------------------------------------------------------------------------
__global__ void k3_sum(float* __restrict__ out)
{
    __shared__ float s[64];
    int t = threadIdx.x;
    s[t] = g_nll[t];
    __syncthreads();
    #pragma unroll
    for (int o = 32; o > 0; o >>= 1) {
        if (t < o) s[t] += s[t + o];
        __syncthreads();
    }
    if (t == 0) out[0] = s[0];
}

extern "C" void kernel_launch(void* const* d_in, const int* in_sizes, int n_in,
                              void* d_out, int out_size)
{
    const float* X      = (const float*)d_in[0];
    const int*   labels = (const int*)  d_in[1];
    const float* W      = (const float*)d_in[2];
    const float* bias   = (const float*)d_in[3];
    const float* trans  = (const float*)d_in[4];
    float* out = (float*)d_out;

    k1_gemm<<<296, 256>>>(X, labels, W, bias, out);
    k2_crf<<<B_, 128>>>(trans, labels, out);
    k3_sum<<<1, 64>>>(out);
}

// round 7
// speedup vs baseline: 1.6071x; 1.6071x over previous
#include <cuda_runtime.h>
#include <math.h>

// Problem constants
#define B_    64
#define L_    512
#define C_    1024
#define NT    7
#define START_ 5
#define STOP_  6
#define NROWS (B_ * L_)   // 32768

// k1 tiling
#define RPB   256                 // rows per block
#define KC    32                  // columns per tile
#define NTILE (C_ / KC)           // 32
#define PADW  36                  // padded floats per smem row (bank-conflict-free)
#define SX_BUF_BYTES (RPB * PADW * 4)            // 36864
#define SW_OFF       (2 * SX_BUF_BYTES)          // W after double buffer
#define SW_BYTES     (NT * (C_ / 2) * 8)         // 28672
#define SB_OFF       (SW_OFF + SW_BYTES)
#define SMEM_BYTES   (SB_OFF + 64)

__device__ float g_nll[B_];

// packed f32x2 FMA (Blackwell; PTX-only form -> single FFMA2)
__device__ __forceinline__ void ffma2(unsigned long long& d,
                                      unsigned long long a,
                                      unsigned long long b) {
    asm("fma.rn.f32x2 %0, %1, %2, %0;" : "+l"(d) : "l"(a), "l"(b));
}
// 128-bit shared load into two 64-bit (f32x2) regs
__device__ __forceinline__ void lds_v2b64(unsigned smem_addr,
                                          unsigned long long& lo,
                                          unsigned long long& hi) {
    asm("ld.shared.v2.b64 {%0, %1}, [%2];" : "=l"(lo), "=l"(hi) : "r"(smem_addr));
}
__device__ __forceinline__ float unpack_sum(unsigned long long v) {
    union { unsigned long long u; float2 f; } cv; cv.u = v;
    return cv.f.x + cv.f.y;
}
__device__ __forceinline__ unsigned smem_u32(const void* p) {
    unsigned a;
    asm("{ .reg .u64 t; cvta.to.shared.u64 t, %1; cvt.u32.u64 %0, t; }"
        : "=r"(a) : "l"(p));
    return a;
}
__device__ __forceinline__ void cp_async16(unsigned dst, const void* src) {
    asm volatile("cp.async.cg.shared.global [%0], [%1], 16;"
                 :: "r"(dst), "l"(src));
}
__device__ __forceinline__ void cp_commit() {
    asm volatile("cp.async.commit_group;");
}
template <int N>
__device__ __forceinline__ void cp_wait() {
    asm volatile("cp.async.wait_group %0;" :: "n"(N));
}

// ---------------------------------------------------------------------------
// Kernel 1: pred = X @ W^T + b.  Thread-per-row, cp.async double-buffered
// X tiles (memory streams continuously), W broadcast from shared, f32x2 FMAs.
// ---------------------------------------------------------------------------
__global__ void __launch_bounds__(256) k1_gemm(
    const float* __restrict__ X, const int* __restrict__ labels,
    const float* __restrict__ W, const float* __restrict__ bias,
    float* __restrict__ out)
{
    extern __shared__ __align__(16) char dsm[];
    unsigned long long* sW2 = (unsigned long long*)(dsm + SW_OFF); // [NT][C_/2]
    float* sb = (float*)(dsm + SB_OFF);
    const unsigned sx_base = smem_u32(dsm);

    const int tid  = threadIdx.x;
    const int row0 = blockIdx.x * RPB;

    // Stage W as f32x2 pairs + bias
    for (int i = tid; i < NT * (C_ / 2); i += 256)
        sW2[i] = ((const unsigned long long*)W)[i];
    if (tid < NT) sb[tid] = bias[tid];

    // ---- tile loader: 2048 x 16B segments, warp covers 4 full 128B lines ----
    const float* xbase = X + (size_t)row0 * C_;
    #define LOAD_TILE(T, BUF) do {                                          \
        const float* sbse = xbase + (T) * KC;                               \
        unsigned dbse = sx_base + (BUF) * SX_BUF_BYTES;                     \
        _Pragma("unroll")                                                   \
        for (int i_ = 0; i_ < 8; i_++) {                                    \
            int seg_ = i_ * 256 + tid;                                      \
            int r_ = seg_ >> 3, j_ = seg_ & 7;                              \
            cp_async16(dbse + r_ * (PADW * 4) + j_ * 16,                    \
                       sbse + (size_t)r_ * C_ + j_ * 4);                    \
        }                                                                   \
    } while (0)

    LOAD_TILE(0, 0);
    cp_commit();

    unsigned long long acc[NT];
    #pragma unroll
    for (int g = 0; g < NT; g++) acc[g] = 0ull;

    for (int t = 0; t < NTILE; t++) {
        const int cur = t & 1;
        if (t + 1 < NTILE) {
            LOAD_TILE(t + 1, cur ^ 1);
            cp_commit();
            cp_wait<1>();
        } else {
            cp_wait<0>();
        }
        __syncthreads();

        const unsigned rbase = sx_base + cur * SX_BUF_BYTES + tid * (PADW * 4);
        const unsigned long long* wrow = sW2 + t * (KC / 2);
        #pragma unroll
        for (int j = 0; j < 8; j++) {
            unsigned long long xlo, xhi;
            lds_v2b64(rbase + j * 16, xlo, xhi);
            #pragma unroll
            for (int g = 0; g < NT; g++) {
                ffma2(acc[g], xlo, wrow[(size_t)g * (C_ / 2) + j * 2]);
                ffma2(acc[g], xhi, wrow[(size_t)g * (C_ / 2) + j * 2 + 1]);
            }
        }
        __syncthreads();
    }

    // Epilogue: bias add + store pred + labels-as-float
    const int grow = row0 + tid;
    float* pred = out + 1 + NROWS;
    #pragma unroll
    for (int g = 0; g < NT; g++)
        pred[(size_t)grow * NT + g] = unpack_sum(acc[g]) + sb[g];
    out[1 + grow] = (float)labels[grow];
    #undef LOAD_TILE
}

// ---------------------------------------------------------------------------
// Kernel 2: CRF forward in exp-domain (chunked matrix products) + gold score.
// One block per batch element; 128 threads = 16 chunks x 8 columns.
// ---------------------------------------------------------------------------
__global__ void __launch_bounds__(128) k2_crf(
    const float* __restrict__ trans,
    const int* __restrict__ labels,
    const float* __restrict__ outbuf)
{
    __shared__ float sEE[L_ * 8];       // 16 KB: exp-emissions for this batch
    __shared__ float sET[8][8];         // exp(transitions), padded
    __shared__ float sT[49];            // raw transitions
    __shared__ float sM[16][8][8];      // chunk matrices: [chunk][col][row]
    __shared__ float sS[16];            // chunk log-scales
    __shared__ float sv[8];
    __shared__ float sgold, svscale;

    const int b   = blockIdx.x;
    const int tid = threadIdx.x;
    const float* pred = outbuf + 1 + NROWS;

    {   // exp(emissions) for this batch, padded [L][8] (col 7 = 0)
        const float* pb = pred + (size_t)b * L_ * NT;
        for (int i = tid; i < L_ * NT; i += 128) {
            int r = i / NT, c = i % NT;
            sEE[r * 8 + c] = expf(pb[i]);
        }
        for (int r = tid; r < L_; r += 128) sEE[r * 8 + 7] = 0.f;
    }
    if (tid < 64) {
        int n = tid >> 3, p = tid & 7;
        sET[n][p] = (n < NT && p < NT) ? expf(trans[n * NT + p]) : 0.f;
    }
    if (tid < 49) sT[tid] = trans[tid];
    __syncthreads();

    // ---- Stage A: per-chunk matrix product (thread per column) ----
    {
        const int chunk = tid >> 3;     // 0..15
        const int col   = tid & 7;      // 0..7 (7 = zero pad column)
        float ET[NT][NT];
        #pragma unroll
        for (int n = 0; n < NT; n++)
            #pragma unroll
            for (int p = 0; p < NT; p++) ET[n][p] = sET[n][p];

        const int t0 = chunk * 32;
        float u[NT];
        #pragma unroll
        for (int n = 0; n < NT; n++)
            u[n] = (col < NT) ? sET[n][col] * sEE[t0 * 8 + n] : 0.f;
        float s = 0.f;

        for (int step = 1; step < 32; step++) {
            const float* ee = &sEE[(t0 + step) * 8];
            float v[NT];
            #pragma unroll
            for (int n = 0; n < NT; n++) {
                float a = ET[n][0] * u[0];
                #pragma unroll
                for (int p = 1; p < NT; p++) a = fmaf(ET[n][p], u[p], a);
                v[n] = a * ee[n];
            }
            #pragma unroll
            for (int n = 0; n < NT; n++) u[n] = v[n];

            if ((step & 7) == 7) {      // renormalize (shared scale per chunk)
                float m = u[0];
                #pragma unroll
                for (int n = 1; n < NT; n++) m = fmaxf(m, u[n]);
                m = fmaxf(m, __shfl_xor_sync(0xffffffffu, m, 1));
                m = fmaxf(m, __shfl_xor_sync(0xffffffffu, m, 2));
                m = fmaxf(m, __shfl_xor_sync(0xffffffffu, m, 4));
                if (m > 0.f) {
                    float inv = 1.f / m;
                    #pragma unroll
                    for (int n = 0; n < NT; n++) u[n] *= inv;
                    s += logf(m);
                }
            }
        }
        #pragma unroll
        for (int n = 0; n < NT; n++) sM[chunk][col][n] = u[n];
        sM[chunk][col][7] = 0.f;
        if (col == 0) sS[chunk] = s;
    }
    __syncthreads();

    // ---- Stage B: sequential matrix-vector combine (warp 0, lanes 0..7),
    //      gold score in parallel on warp 1 ----
    if (tid < 8) {
        const int n = tid;
        float v     = sM[0][START_][n];   // init vector = e_START
        float scale = sS[0];
        for (int c = 1; c < 16; c++) {
            sv[n] = v;
            __syncwarp(0x000000ffu);
            float a = 0.f;
            #pragma unroll
            for (int j = 0; j < NT; j++) a = fmaf(sM[c][j][n], sv[j], a);
            float m = a;
            m = fmaxf(m, __shfl_xor_sync(0xffu, m, 1));
            m = fmaxf(m, __shfl_xor_sync(0xffu, m, 2));
            m = fmaxf(m, __shfl_xor_sync(0xffu, m, 4));
            if (m > 0.f) { v = a / m; scale += logf(m); }
            else         { v = a; }
            scale += sS[c];
            __syncwarp(0x000000ffu);
        }
        sv[n] = v;
        if (n == 0) svscale = scale;
    } else if (tid >= 32 && tid < 64) {
        const int lane = tid - 32;
        const int base = b * L_;
        float acc = 0.f;
        #pragma unroll 4
        for (int k = 0; k < 16; k++) {
            int t   = lane + k * 32;
            int tag = labels[base + t];
            int pt  = (t == 0) ? START_ : labels[base + t - 1];
            acc += pred[(size_t)(base + t) * NT + tag] + sT[tag * NT + pt];
        }
        #pragma unroll
        for (int o = 16; o > 0; o >>= 1)
            acc += __shfl_xor_sync(0xffffffffu, acc, o);
        if (lane == 0) sgold = acc + sT[STOP_ * NT + labels[base + L_ - 1]];
    }
    __syncthreads();

    if (tid == 0) {
        float sum = 0.f;
        #pragma unroll
        for (int n = 0; n < NT; n++) sum += sv[n] * sET[STOP_][n];
        g_nll[b] = logf(sum) + svscale - sgold;
    }
}

// ---------------------------------------------------------------------------
// Kernel 3: deterministic sum of 64 per-batch NLLs -> d_out[0]
// ---------------------------------------------------------------------------
__global__ void k3_sum(float* __restrict__ out)
{
    __shared__ float s[64];
    int t = threadIdx.x;
    s[t] = g_nll[t];
    __syncthreads();
    #pragma unroll
    for (int o = 32; o > 0; o >>= 1) {
        if (t < o) s[t] += s[t + o];
        __syncthreads();
    }
    if (t == 0) out[0] = s[0];
}

extern "C" void kernel_launch(void* const* d_in, const int* in_sizes, int n_in,
                              void* d_out, int out_size)
{
    const float* X      = (const float*)d_in[0];
    const int*   labels = (const int*)  d_in[1];
    const float* W      = (const float*)d_in[2];
    const float* bias   = (const float*)d_in[3];
    const float* trans  = (const float*)d_in[4];
    float* out = (float*)d_out;

    static int smem_cfg = 0;
    if (!smem_cfg) {
        cudaFuncSetAttribute(k1_gemm,
                             cudaFuncAttributeMaxDynamicSharedMemorySize,
                             SMEM_BYTES);
        smem_cfg = 1;
    }

    k1_gemm<<<NROWS / RPB, 256, SMEM_BYTES>>>(X, labels, W, bias, out);
    k2_crf<<<B_, 128>>>(trans, labels, out);
    k3_sum<<<1, 64>>>(out);
}

// round 8
// speedup vs baseline: 1.7838x; 1.1100x over previous
#include <cuda_runtime.h>
#include <math.h>

// Problem constants
#define B_    64
#define L_    512
#define C_    1024
#define NT    7
#define START_ 5
#define STOP_  6
#define NROWS (B_ * L_)   // 32768

// k1 tiling: 128 rows/block, 32-col tiles, 4-deep cp.async ring
#define RPB   128
#define TPB   128
#define KC    32
#define NTILE (C_ / KC)           // 32
#define NSTG  4                   // pipeline stages
#define PADW  36                  // padded floats per smem row (conflict-free)
#define SX_STG_BYTES (RPB * PADW * 4)            // 18432
#define SW_OFF       (NSTG * SX_STG_BYTES)       // 73728
#define SW_BYTES     (NT * (C_ / 2) * 8)         // 28672
#define SB_OFF       (SW_OFF + SW_BYTES)
#define SMEM_BYTES   (SB_OFF + 64)               // ~102.5 KB -> 2 blocks/SM

__device__ float g_nll[B_];

// packed f32x2 FMA (Blackwell; PTX-only form -> single FFMA2)
__device__ __forceinline__ void ffma2(unsigned long long& d,
                                      unsigned long long a,
                                      unsigned long long b) {
    asm("fma.rn.f32x2 %0, %1, %2, %0;" : "+l"(d) : "l"(a), "l"(b));
}
// 128-bit shared load into two 64-bit (f32x2) regs
__device__ __forceinline__ void lds_v2b64(unsigned smem_addr,
                                          unsigned long long& lo,
                                          unsigned long long& hi) {
    asm("ld.shared.v2.b64 {%0, %1}, [%2];" : "=l"(lo), "=l"(hi) : "r"(smem_addr));
}
__device__ __forceinline__ float unpack_sum(unsigned long long v) {
    union { unsigned long long u; float2 f; } cv; cv.u = v;
    return cv.f.x + cv.f.y;
}
__device__ __forceinline__ unsigned smem_u32(const void* p) {
    unsigned a;
    asm("{ .reg .u64 t; cvta.to.shared.u64 t, %1; cvt.u32.u64 %0, t; }"
        : "=r"(a) : "l"(p));
    return a;
}
__device__ __forceinline__ void cp_async16(unsigned dst, const void* src) {
    asm volatile("cp.async.cg.shared.global [%0], [%1], 16;"
                 :: "r"(dst), "l"(src));
}
__device__ __forceinline__ void cp_commit() {
    asm volatile("cp.async.commit_group;");
}
template <int N>
__device__ __forceinline__ void cp_wait() {
    asm volatile("cp.async.wait_group %0;" :: "n"(N));
}

// ---------------------------------------------------------------------------
// Kernel 1: pred = X @ W^T + b.  Thread-per-row, 4-deep cp.async pipeline
// (3 tiles in flight ahead -> DRAM latency hidden), W broadcast from shared,
// f32x2 FMAs.  grid=256 blocks x 128 thr, 2 blocks/SM.
// ---------------------------------------------------------------------------
__global__ void __launch_bounds__(TPB) k1_gemm(
    const float* __restrict__ X, const int* __restrict__ labels,
    const float* __restrict__ W, const float* __restrict__ bias,
    float* __restrict__ out)
{
    extern __shared__ __align__(16) char dsm[];
    unsigned long long* sW2 = (unsigned long long*)(dsm + SW_OFF); // [NT][C_/2]
    float* sb = (float*)(dsm + SB_OFF);
    const unsigned sx_base = smem_u32(dsm);

    const int tid  = threadIdx.x;
    const int row0 = blockIdx.x * RPB;

    // Stage W as f32x2 pairs + bias
    for (int i = tid; i < NT * (C_ / 2); i += TPB)
        sW2[i] = ((const unsigned long long*)W)[i];
    if (tid < NT) sb[tid] = bias[tid];

    // ---- tile loader: 1024 x 16B segments; warp covers 4 full 128B lines ----
    const float* xbase = X + (size_t)row0 * C_;
    #define LOAD_TILE(T, BUF) do {                                          \
        const float* sbse = xbase + (T) * KC;                               \
        unsigned dbse = sx_base + (BUF) * SX_STG_BYTES;                     \
        _Pragma("unroll")                                                   \
        for (int i_ = 0; i_ < 8; i_++) {                                    \
            int seg_ = i_ * TPB + tid;                                      \
            int r_ = seg_ >> 3, j_ = seg_ & 7;                              \
            cp_async16(dbse + r_ * (PADW * 4) + j_ * 16,                    \
                       sbse + (size_t)r_ * C_ + j_ * 4);                    \
        }                                                                   \
    } while (0)

    // Prologue: fill 3 stages ahead
    LOAD_TILE(0, 0); cp_commit();
    LOAD_TILE(1, 1); cp_commit();
    LOAD_TILE(2, 2); cp_commit();

    unsigned long long acc[NT];
    #pragma unroll
    for (int g = 0; g < NT; g++) acc[g] = 0ull;

    for (int t = 0; t < NTILE; t++) {
        // Issue tile t+3 into buffer (t+3)&3 (= buffer of tile t-1, already
        // consumed; previous iteration ended with __syncthreads).
        if (t + 3 < NTILE) {
            LOAD_TILE(t + 3, (t + 3) & (NSTG - 1));
            cp_commit();
            cp_wait<3>();       // oldest (tile t) complete
        } else {
            cp_wait<0>();
        }
        __syncthreads();

        const unsigned rbase = sx_base + (t & (NSTG - 1)) * SX_STG_BYTES
                             + tid * (PADW * 4);
        const unsigned long long* wrow = sW2 + t * (KC / 2);
        #pragma unroll
        for (int j = 0; j < 8; j++) {
            unsigned long long xlo, xhi;
            lds_v2b64(rbase + j * 16, xlo, xhi);
            #pragma unroll
            for (int g = 0; g < NT; g++) {
                ffma2(acc[g], xlo, wrow[(size_t)g * (C_ / 2) + j * 2]);
                ffma2(acc[g], xhi, wrow[(size_t)g * (C_ / 2) + j * 2 + 1]);
            }
        }
        __syncthreads();
    }

    // Epilogue: bias add + store pred + labels-as-float
    const int grow = row0 + tid;
    float* pred = out + 1 + NROWS;
    #pragma unroll
    for (int g = 0; g < NT; g++)
        pred[(size_t)grow * NT + g] = unpack_sum(acc[g]) + sb[g];
    out[1 + grow] = (float)labels[grow];
    #undef LOAD_TILE
}

// ---------------------------------------------------------------------------
// Kernel 2: CRF forward in exp-domain (chunked matrix products) + gold score.
// One block per batch element; 128 threads = 16 chunks x 8 columns.
// ---------------------------------------------------------------------------
__global__ void __launch_bounds__(128) k2_crf(
    const float* __restrict__ trans,
    const int* __restrict__ labels,
    const float* __restrict__ outbuf)
{
    __shared__ float sEE[L_ * 8];       // 16 KB: exp-emissions for this batch
    __shared__ float sET[8][8];         // exp(transitions), padded
    __shared__ float sT[49];            // raw transitions
    __shared__ float sM[16][8][8];      // chunk matrices: [chunk][col][row]
    __shared__ float sS[16];            // chunk log-scales
    __shared__ float sv[8];
    __shared__ float sgold, svscale;

    const int b   = blockIdx.x;
    const int tid = threadIdx.x;
    const float* pred = outbuf + 1 + NROWS;

    {   // exp(emissions) for this batch, padded [L][8] (col 7 = 0)
        const float* pb = pred + (size_t)b * L_ * NT;
        for (int i = tid; i < L_ * NT; i += 128) {
            int r = i / NT, c = i % NT;
            sEE[r * 8 + c] = expf(pb[i]);
        }
        for (int r = tid; r < L_; r += 128) sEE[r * 8 + 7] = 0.f;
    }
    if (tid < 64) {
        int n = tid >> 3, p = tid & 7;
        sET[n][p] = (n < NT && p < NT) ? expf(trans[n * NT + p]) : 0.f;
    }
    if (tid < 49) sT[tid] = trans[tid];
    __syncthreads();

    // ---- Stage A: per-chunk matrix product (thread per column) ----
    {
        const int chunk = tid >> 3;     // 0..15
        const int col   = tid & 7;      // 0..7 (7 = zero pad column)
        float ET[NT][NT];
        #pragma unroll
        for (int n = 0; n < NT; n++)
            #pragma unroll
            for (int p = 0; p < NT; p++) ET[n][p] = sET[n][p];

        const int t0 = chunk * 32;
        float u[NT];
        #pragma unroll
        for (int n = 0; n < NT; n++)
            u[n] = (col < NT) ? sET[n][col] * sEE[t0 * 8 + n] : 0.f;
        float s = 0.f;

        for (int step = 1; step < 32; step++) {
            const float* ee = &sEE[(t0 + step) * 8];
            float v[NT];
            #pragma unroll
            for (int n = 0; n < NT; n++) {
                float a = ET[n][0] * u[0];
                #pragma unroll
                for (int p = 1; p < NT; p++) a = fmaf(ET[n][p], u[p], a);
                v[n] = a * ee[n];
            }
            #pragma unroll
            for (int n = 0; n < NT; n++) u[n] = v[n];

            if ((step & 7) == 7) {      // renormalize (shared scale per chunk)
                float m = u[0];
                #pragma unroll
                for (int n = 1; n < NT; n++) m = fmaxf(m, u[n]);
                m = fmaxf(m, __shfl_xor_sync(0xffffffffu, m, 1));
                m = fmaxf(m, __shfl_xor_sync(0xffffffffu, m, 2));
                m = fmaxf(m, __shfl_xor_sync(0xffffffffu, m, 4));
                if (m > 0.f) {
                    float inv = 1.f / m;
                    #pragma unroll
                    for (int n = 0; n < NT; n++) u[n] *= inv;
                    s += logf(m);
                }
            }
        }
        #pragma unroll
        for (int n = 0; n < NT; n++) sM[chunk][col][n] = u[n];
        sM[chunk][col][7] = 0.f;
        if (col == 0) sS[chunk] = s;
    }
    __syncthreads();

    // ---- Stage B: sequential matrix-vector combine (warp 0, lanes 0..7),
    //      gold score in parallel on warp 1 ----
    if (tid < 8) {
        const int n = tid;
        float v     = sM[0][START_][n];   // init vector = e_START
        float scale = sS[0];
        for (int c = 1; c < 16; c++) {
            sv[n] = v;
            __syncwarp(0x000000ffu);
            float a = 0.f;
            #pragma unroll
            for (int j = 0; j < NT; j++) a = fmaf(sM[c][j][n], sv[j], a);
            float m = a;
            m = fmaxf(m, __shfl_xor_sync(0xffu, m, 1));
            m = fmaxf(m, __shfl_xor_sync(0xffu, m, 2));
            m = fmaxf(m, __shfl_xor_sync(0xffu, m, 4));
            if (m > 0.f) { v = a / m; scale += logf(m); }
            else         { v = a; }
            scale += sS[c];
            __syncwarp(0x000000ffu);
        }
        sv[n] = v;
        if (n == 0) svscale = scale;
    } else if (tid >= 32 && tid < 64) {
        const int lane = tid - 32;
        const int base = b * L_;
        float acc = 0.f;
        #pragma unroll 4
        for (int k = 0; k < 16; k++) {
            int t   = lane + k * 32;
            int tag = labels[base + t];
            int pt  = (t == 0) ? START_ : labels[base + t - 1];
            acc += pred[(size_t)(base + t) * NT + tag] + sT[tag * NT + pt];
        }
        #pragma unroll
        for (int o = 16; o > 0; o >>= 1)
            acc += __shfl_xor_sync(0xffffffffu, acc, o);
        if (lane == 0) sgold = acc + sT[STOP_ * NT + labels[base + L_ - 1]];
    }
    __syncthreads();

    if (tid == 0) {
        float sum = 0.f;
        #pragma unroll
        for (int n = 0; n < NT; n++) sum += sv[n] * sET[STOP_][n];
        g_nll[b] = logf(sum) + svscale - sgold;
    }
}

// ---------------------------------------------------------------------------
// Kernel 3: deterministic sum of 64 per-batch NLLs -> d_out[0]
// ---------------------------------------------------------------------------
__global__ void k3_sum(float* __restrict__ out)
{
    __shared__ float s[64];
    int t = threadIdx.x;
    s[t] = g_nll[t];
    __syncthreads();
    #pragma unroll
    for (int o = 32; o > 0; o >>= 1) {
        if (t < o) s[t] += s[t + o];
        __syncthreads();
    }
    if (t == 0) out[0] = s[0];
}

extern "C" void kernel_launch(void* const* d_in, const int* in_sizes, int n_in,
                              void* d_out, int out_size)
{
    const float* X      = (const float*)d_in[0];
    const int*   labels = (const int*)  d_in[1];
    const float* W      = (const float*)d_in[2];
    const float* bias   = (const float*)d_in[3];
    const float* trans  = (const float*)d_in[4];
    float* out = (float*)d_out;

    static int smem_cfg = 0;
    if (!smem_cfg) {
        cudaFuncSetAttribute(k1_gemm,
                             cudaFuncAttributeMaxDynamicSharedMemorySize,
                             SMEM_BYTES);
        smem_cfg = 1;
    }

    k1_gemm<<<NROWS / RPB, TPB, SMEM_BYTES>>>(X, labels, W, bias, out);
    k2_crf<<<B_, 128>>>(trans, labels, out);
    k3_sum<<<1, 64>>>(out);
}

// round 9
// speedup vs baseline: 1.8127x; 1.0162x over previous
#include <cuda_runtime.h>
#include <math.h>

// Problem constants
#define B_    64
#define L_    512
#define C_    1024
#define NT    7
#define START_ 5
#define STOP_  6
#define NROWS (B_ * L_)   // 32768

// k1 tiling: 128 rows/block (4 warps x 32 rows), 32-col tiles,
// 4-deep PER-WARP cp.async ring (no block barriers in the mainloop).
#define RPB   128
#define TPB   128
#define KC    32
#define NTILE (C_ / KC)           // 32
#define NSTG  4
#define PADW  36                  // padded floats per smem row (conflict-free)
#define WSTG_BYTES (32 * PADW * 4)               // 4608 per warp-stage
#define SW_OFF     (4 * NSTG * WSTG_BYTES)       // 73728 (4 warps)
#define SW_BYTES   (NT * (C_ / 2) * 8)           // 28672
#define SB_OFF     (SW_OFF + SW_BYTES)
#define SMEM_BYTES (SB_OFF + 64)                 // ~102.5 KB -> 2 blocks/SM

__device__ float g_nll[B_];
__device__ int   g_cnt;          // zero-init; self-resetting each run

// packed f32x2 FMA (Blackwell; PTX-only form -> single FFMA2)
__device__ __forceinline__ void ffma2(unsigned long long& d,
                                      unsigned long long a,
                                      unsigned long long b) {
    asm("fma.rn.f32x2 %0, %1, %2, %0;" : "+l"(d) : "l"(a), "l"(b));
}
__device__ __forceinline__ void lds_v2b64(unsigned smem_addr,
                                          unsigned long long& lo,
                                          unsigned long long& hi) {
    asm volatile("ld.shared.v2.b64 {%0, %1}, [%2];"
                 : "=l"(lo), "=l"(hi) : "r"(smem_addr));
}
__device__ __forceinline__ float unpack_sum(unsigned long long v) {
    union { unsigned long long u; float2 f; } cv; cv.u = v;
    return cv.f.x + cv.f.y;
}
__device__ __forceinline__ unsigned smem_u32(const void* p) {
    unsigned a;
    asm("{ .reg .u64 t; cvta.to.shared.u64 t, %1; cvt.u32.u64 %0, t; }"
        : "=r"(a) : "l"(p));
    return a;
}
__device__ __forceinline__ void cp_async16(unsigned dst, const void* src) {
    asm volatile("cp.async.cg.shared.global [%0], [%1], 16;"
                 :: "r"(dst), "l"(src));
}
__device__ __forceinline__ void cp_commit() {
    asm volatile("cp.async.commit_group;");
}
template <int N>
__device__ __forceinline__ void cp_wait() {
    asm volatile("cp.async.wait_group %0;" :: "n"(N));
}

// ---------------------------------------------------------------------------
// Kernel 1: pred = X @ W^T + b.  Thread-per-row; each WARP owns a private
// 4-deep cp.async pipeline over its 32 rows -> no block barriers, warps
// stream memory continuously. W broadcast from shared, f32x2 FMAs.
// ---------------------------------------------------------------------------
__global__ void __launch_bounds__(TPB) k1_gemm(
    const float* __restrict__ X, const int* __restrict__ labels,
    const float* __restrict__ W, const float* __restrict__ bias,
    float* __restrict__ out)
{
    extern __shared__ __align__(16) char dsm[];
    unsigned long long* sW2 = (unsigned long long*)(dsm + SW_OFF); // [NT][C_/2]
    float* sb = (float*)(dsm + SB_OFF);
    const unsigned sx_base = smem_u32(dsm);

    const int tid  = threadIdx.x;
    const int wid  = tid >> 5;
    const int lane = tid & 31;

    // Stage W as f32x2 pairs + bias (one block-wide sync, then barrier-free)
    for (int i = tid; i < NT * (C_ / 2); i += TPB)
        sW2[i] = ((const unsigned long long*)W)[i];
    if (tid < NT) sb[tid] = bias[tid];
    __syncthreads();

    const int wrow0 = blockIdx.x * RPB + wid * 32;
    const float* xw = X + (size_t)wrow0 * C_;
    const unsigned wbase = sx_base + wid * (NSTG * WSTG_BYTES);

    // Per-warp tile loader: 32 rows x 128B; lanes 0-7 cover row r contiguously
    // (8 x 16B = full 128B line per 8-lane group -> perfectly coalesced).
    #define LOAD_TILE(T, BUF) do {                                          \
        const float* sbse = xw + (T) * KC;                                  \
        unsigned dbse = wbase + (BUF) * WSTG_BYTES;                         \
        _Pragma("unroll")                                                   \
        for (int i_ = 0; i_ < 8; i_++) {                                    \
            int seg_ = i_ * 32 + lane;                                      \
            int r_ = seg_ >> 3, j_ = seg_ & 7;                              \
            cp_async16(dbse + r_ * (PADW * 4) + j_ * 16,                    \
                       sbse + (size_t)r_ * C_ + j_ * 4);                    \
        }                                                                   \
    } while (0)

    LOAD_TILE(0, 0); cp_commit();
    LOAD_TILE(1, 1); cp_commit();
    LOAD_TILE(2, 2); cp_commit();

    unsigned long long acc[NT];
    #pragma unroll
    for (int g = 0; g < NT; g++) acc[g] = 0ull;

    for (int t = 0; t < NTILE; t++) {
        if (t + 3 < NTILE) {
            LOAD_TILE(t + 3, (t + 3) & (NSTG - 1));
            cp_commit();
            cp_wait<3>();
        } else {
            cp_wait<0>();
        }
        __syncwarp();   // all lanes' groups drained -> whole tile present

        const unsigned rbase = wbase + (t & (NSTG - 1)) * WSTG_BYTES
                             + lane * (PADW * 4);
        const unsigned long long* wrow = sW2 + t * (KC / 2);
        #pragma unroll
        for (int j = 0; j < 8; j++) {
            unsigned long long xlo, xhi;
            lds_v2b64(rbase + j * 16, xlo, xhi);
            #pragma unroll
            for (int g = 0; g < NT; g++) {
                ffma2(acc[g], xlo, wrow[(size_t)g * (C_ / 2) + j * 2]);
                ffma2(acc[g], xhi, wrow[(size_t)g * (C_ / 2) + j * 2 + 1]);
            }
        }
        __syncwarp();
    }

    // Epilogue: bias add + store pred + labels-as-float
    const int grow = wrow0 + lane;
    float* pred = out + 1 + NROWS;
    #pragma unroll
    for (int g = 0; g < NT; g++)
        pred[(size_t)grow * NT + g] = unpack_sum(acc[g]) + sb[g];
    out[1 + grow] = (float)labels[grow];
    #undef LOAD_TILE
}

// ---------------------------------------------------------------------------
// Kernel 2: CRF forward (exp-domain chunked matrix products) + gold score
// + fused final reduction ("last block out", deterministic tid-ordered sum).
// One block per batch element; 128 threads = 16 chunks x 8 columns.
// ---------------------------------------------------------------------------
__global__ void __launch_bounds__(128) k2_crf(
    const float* __restrict__ trans,
    const int* __restrict__ labels,
    float* __restrict__ outbuf)
{
    __shared__ float sEE[L_ * 8];       // 16 KB: exp-emissions for this batch
    __shared__ float sET[8][8];         // exp(transitions), padded
    __shared__ float sT[49];            // raw transitions
    __shared__ float sM[16][8][8];      // chunk matrices: [chunk][col][row]
    __shared__ float sS[16];            // chunk log-scales
    __shared__ float sv[8];
    __shared__ float sgold, svscale;
    __shared__ int   slast;

    const int b   = blockIdx.x;
    const int tid = threadIdx.x;
    const float* pred = outbuf + 1 + NROWS;

    {   // exp(emissions) for this batch, padded [L][8] (col 7 = 0)
        const float* pb = pred + (size_t)b * L_ * NT;
        for (int i = tid; i < L_ * NT; i += 128) {
            int r = i / NT, c = i % NT;
            sEE[r * 8 + c] = expf(pb[i]);
        }
        for (int r = tid; r < L_; r += 128) sEE[r * 8 + 7] = 0.f;
    }
    if (tid < 64) {
        int n = tid >> 3, p = tid & 7;
        sET[n][p] = (n < NT && p < NT) ? expf(trans[n * NT + p]) : 0.f;
    }
    if (tid < 49) sT[tid] = trans[tid];
    __syncthreads();

    // ---- Stage A: per-chunk matrix product (thread per column) ----
    {
        const int chunk = tid >> 3;     // 0..15
        const int col   = tid & 7;      // 0..7 (7 = zero pad column)
        float ET[NT][NT];
        #pragma unroll
        for (int n = 0; n < NT; n++)
            #pragma unroll
            for (int p = 0; p < NT; p++) ET[n][p] = sET[n][p];

        const int t0 = chunk * 32;
        float u[NT];
        #pragma unroll
        for (int n = 0; n < NT; n++)
            u[n] = (col < NT) ? sET[n][col] * sEE[t0 * 8 + n] : 0.f;
        float s = 0.f;

        for (int step = 1; step < 32; step++) {
            const float* ee = &sEE[(t0 + step) * 8];
            float v[NT];
            #pragma unroll
            for (int n = 0; n < NT; n++) {
                float a = ET[n][0] * u[0];
                #pragma unroll
                for (int p = 1; p < NT; p++) a = fmaf(ET[n][p], u[p], a);
                v[n] = a * ee[n];
            }
            #pragma unroll
            for (int n = 0; n < NT; n++) u[n] = v[n];

            if ((step & 7) == 7) {      // renormalize (shared scale per chunk)
                float m = u[0];
                #pragma unroll
                for (int n = 1; n < NT; n++) m = fmaxf(m, u[n]);
                m = fmaxf(m, __shfl_xor_sync(0xffffffffu, m, 1));
                m = fmaxf(m, __shfl_xor_sync(0xffffffffu, m, 2));
                m = fmaxf(m, __shfl_xor_sync(0xffffffffu, m, 4));
                if (m > 0.f) {
                    float inv = 1.f / m;
                    #pragma unroll
                    for (int n = 0; n < NT; n++) u[n] *= inv;
                    s += logf(m);
                }
            }
        }
        #pragma unroll
        for (int n = 0; n < NT; n++) sM[chunk][col][n] = u[n];
        sM[chunk][col][7] = 0.f;
        if (col == 0) sS[chunk] = s;
    }
    __syncthreads();

    // ---- Stage B: sequential matrix-vector combine (warp 0, lanes 0..7),
    //      gold score in parallel on warp 1 ----
    if (tid < 8) {
        const int n = tid;
        float v     = sM[0][START_][n];   // init vector = e_START
        float scale = sS[0];
        for (int c = 1; c < 16; c++) {
            sv[n] = v;
            __syncwarp(0x000000ffu);
            float a = 0.f;
            #pragma unroll
            for (int j = 0; j < NT; j++) a = fmaf(sM[c][j][n], sv[j], a);
            float m = a;
            m = fmaxf(m, __shfl_xor_sync(0xffu, m, 1));
            m = fmaxf(m, __shfl_xor_sync(0xffu, m, 2));
            m = fmaxf(m, __shfl_xor_sync(0xffu, m, 4));
            if (m > 0.f) { v = a / m; scale += logf(m); }
            else         { v = a; }
            scale += sS[c];
            __syncwarp(0x000000ffu);
        }
        sv[n] = v;
        if (n == 0) svscale = scale;
    } else if (tid >= 32 && tid < 64) {
        const int lane = tid - 32;
        const int base = b * L_;
        float acc = 0.f;
        #pragma unroll 4
        for (int k = 0; k < 16; k++) {
            int t   = lane + k * 32;
            int tag = labels[base + t];
            int pt  = (t == 0) ? START_ : labels[base + t - 1];
            acc += pred[(size_t)(base + t) * NT + tag] + sT[tag * NT + pt];
        }
        #pragma unroll
        for (int o = 16; o > 0; o >>= 1)
            acc += __shfl_xor_sync(0xffffffffu, acc, o);
        if (lane == 0) sgold = acc + sT[STOP_ * NT + labels[base + L_ - 1]];
    }
    __syncthreads();

    if (tid == 0) {
        float sum = 0.f;
        #pragma unroll
        for (int n = 0; n < NT; n++) sum += sv[n] * sET[STOP_][n];
        g_nll[b] = logf(sum) + svscale - sgold;
        __threadfence();
        slast = (atomicAdd(&g_cnt, 1) == B_ - 1);
    }
    __syncthreads();

    // Last block: deterministic tid-ordered sum of all 64 NLLs -> out[0]
    if (slast) {
        __shared__ float sred[64];
        __threadfence();
        if (tid < 64) sred[tid] = *((volatile float*)&g_nll[tid]);
        __syncthreads();
        if (tid < 32) sred[tid] += sred[tid + 32];
        __syncthreads();
        if (tid == 0) {
            float s = 0.f;
            #pragma unroll
            for (int i = 0; i < 32; i++) s += sred[i];
            outbuf[0] = s;
            g_cnt = 0;          // reset for next graph replay
        }
    }
}

extern "C" void kernel_launch(void* const* d_in, const int* in_sizes, int n_in,
                              void* d_out, int out_size)
{
    const float* X      = (const float*)d_in[0];
    const int*   labels = (const int*)  d_in[1];
    const float* W      = (const float*)d_in[2];
    const float* bias   = (const float*)d_in[3];
    const float* trans  = (const float*)d_in[4];
    float* out = (float*)d_out;

    static int smem_cfg = 0;
    if (!smem_cfg) {
        cudaFuncSetAttribute(k1_gemm,
                             cudaFuncAttributeMaxDynamicSharedMemorySize,
                             SMEM_BYTES);
        smem_cfg = 1;
    }

    k1_gemm<<<NROWS / RPB, TPB, SMEM_BYTES>>>(X, labels, W, bias, out);
    k2_crf<<<B_, 128>>>(trans, labels, out);
}

// round 10
// speedup vs baseline: 1.9516x; 1.0766x over previous
#include <cuda_runtime.h>
#include <math.h>

// Problem constants
#define B_    64
#define L_    512
#define C_    1024
#define NT    7
#define START_ 5
#define STOP_  6
#define NROWS (B_ * L_)   // 32768

// k1 tiling: 128 rows/block (4 warps x 32 rows), 32-col tiles,
// 4-deep PER-WARP cp.async ring (no block barriers in the mainloop).
#define RPB   128
#define TPB   128
#define KC    32
#define NTILE (C_ / KC)           // 32
#define NSTG  4
#define PADW  36                  // padded floats per smem row (conflict-free)
#define WSTG_BYTES (32 * PADW * 4)               // 4608 per warp-stage
#define SW_OFF     (4 * NSTG * WSTG_BYTES)       // 73728 (4 warps)
#define SW_BYTES   (NT * (C_ / 2) * 8)           // 28672
#define SB_OFF     (SW_OFF + SW_BYTES)
#define SMEM_BYTES (SB_OFF + 64)                 // ~102.5 KB -> 2 blocks/SM

__device__ float g_nll[B_];
__device__ int   g_cnt;          // zero-init; self-resetting each run

// packed f32x2 FMA (Blackwell; PTX-only form -> single FFMA2)
__device__ __forceinline__ void ffma2(unsigned long long& d,
                                      unsigned long long a,
                                      unsigned long long b) {
    asm("fma.rn.f32x2 %0, %1, %2, %0;" : "+l"(d) : "l"(a), "l"(b));
}
__device__ __forceinline__ void lds_v2b64(unsigned smem_addr,
                                          unsigned long long& lo,
                                          unsigned long long& hi) {
    asm volatile("ld.shared.v2.b64 {%0, %1}, [%2];"
                 : "=l"(lo), "=l"(hi) : "r"(smem_addr));
}
__device__ __forceinline__ float unpack_sum(unsigned long long v) {
    union { unsigned long long u; float2 f; } cv; cv.u = v;
    return cv.f.x + cv.f.y;
}
__device__ __forceinline__ unsigned smem_u32(const void* p) {
    unsigned a;
    asm("{ .reg .u64 t; cvta.to.shared.u64 t, %1; cvt.u32.u64 %0, t; }"
        : "=r"(a) : "l"(p));
    return a;
}
__device__ __forceinline__ void cp_async16(unsigned dst, const void* src) {
    asm volatile("cp.async.cg.shared.global [%0], [%1], 16;"
                 :: "r"(dst), "l"(src));
}
__device__ __forceinline__ void cp_commit() {
    asm volatile("cp.async.commit_group;");
}
template <int N>
__device__ __forceinline__ void cp_wait() {
    asm volatile("cp.async.wait_group %0;" :: "n"(N));
}

// ---------------------------------------------------------------------------
// Kernel 1: pred = X @ W^T + b.  Thread-per-row; each WARP owns a private
// 4-deep cp.async pipeline over its 32 rows -> no block barriers, warps
// stream memory continuously. W broadcast from shared, f32x2 FMAs.
// ---------------------------------------------------------------------------
__global__ void __launch_bounds__(TPB) k1_gemm(
    const float* __restrict__ X, const int* __restrict__ labels,
    const float* __restrict__ W, const float* __restrict__ bias,
    float* __restrict__ out)
{
    extern __shared__ __align__(16) char dsm[];
    unsigned long long* sW2 = (unsigned long long*)(dsm + SW_OFF); // [NT][C_/2]
    float* sb = (float*)(dsm + SB_OFF);
    const unsigned sx_base = smem_u32(dsm);

    const int tid  = threadIdx.x;
    const int wid  = tid >> 5;
    const int lane = tid & 31;

    // Stage W as f32x2 pairs + bias (one block-wide sync, then barrier-free)
    for (int i = tid; i < NT * (C_ / 2); i += TPB)
        sW2[i] = ((const unsigned long long*)W)[i];
    if (tid < NT) sb[tid] = bias[tid];
    __syncthreads();

    const int wrow0 = blockIdx.x * RPB + wid * 32;
    const float* xw = X + (size_t)wrow0 * C_;
    const unsigned wbase = sx_base + wid * (NSTG * WSTG_BYTES);

    // Per-warp tile loader: 32 rows x 128B; lanes 0-7 cover row r contiguously
    #define LOAD_TILE(T, BUF) do {                                          \
        const float* sbse = xw + (T) * KC;                                  \
        unsigned dbse = wbase + (BUF) * WSTG_BYTES;                         \
        _Pragma("unroll")                                                   \
        for (int i_ = 0; i_ < 8; i_++) {                                    \
            int seg_ = i_ * 32 + lane;                                      \
            int r_ = seg_ >> 3, j_ = seg_ & 7;                              \
            cp_async16(dbse + r_ * (PADW * 4) + j_ * 16,                    \
                       sbse + (size_t)r_ * C_ + j_ * 4);                    \
        }                                                                   \
    } while (0)

    LOAD_TILE(0, 0); cp_commit();
    LOAD_TILE(1, 1); cp_commit();
    LOAD_TILE(2, 2); cp_commit();

    unsigned long long acc[NT];
    #pragma unroll
    for (int g = 0; g < NT; g++) acc[g] = 0ull;

    for (int t = 0; t < NTILE; t++) {
        if (t + 3 < NTILE) {
            LOAD_TILE(t + 3, (t + 3) & (NSTG - 1));
            cp_commit();
            cp_wait<3>();
        } else {
            cp_wait<0>();
        }
        __syncwarp();   // all lanes' groups drained -> whole tile present

        const unsigned rbase = wbase + (t & (NSTG - 1)) * WSTG_BYTES
                             + lane * (PADW * 4);
        const unsigned long long* wrow = sW2 + t * (KC / 2);
        #pragma unroll
        for (int j = 0; j < 8; j++) {
            unsigned long long xlo, xhi;
            lds_v2b64(rbase + j * 16, xlo, xhi);
            #pragma unroll
            for (int g = 0; g < NT; g++) {
                ffma2(acc[g], xlo, wrow[(size_t)g * (C_ / 2) + j * 2]);
                ffma2(acc[g], xhi, wrow[(size_t)g * (C_ / 2) + j * 2 + 1]);
            }
        }
        __syncwarp();
    }

    // Epilogue: bias add + store pred + labels-as-float
    const int grow = wrow0 + lane;
    float* pred = out + 1 + NROWS;
    #pragma unroll
    for (int g = 0; g < NT; g++)
        pred[(size_t)grow * NT + g] = unpack_sum(acc[g]) + sb[g];
    out[1 + grow] = (float)labels[grow];
    #undef LOAD_TILE
}

// ---------------------------------------------------------------------------
// Kernel 2: CRF forward (exp-domain chunked matrix products) + gold score
// + fused final reduction.  MUFU intrinsics (__expf/__logf) and sparse
// Stage-B renormalization to cut serial latency.
// ---------------------------------------------------------------------------
__global__ void __launch_bounds__(128) k2_crf(
    const float* __restrict__ trans,
    const int* __restrict__ labels,
    float* __restrict__ outbuf)
{
    __shared__ float sEE[L_ * 8];       // 16 KB: exp-emissions for this batch
    __shared__ float sET[8][8];         // exp(transitions), padded
    __shared__ float sT[49];            // raw transitions
    __shared__ float sM[16][8][8];      // chunk matrices: [chunk][col][row]
    __shared__ float sS[16];            // chunk log-scales
    __shared__ float sv[8];
    __shared__ float sgold, svscale;
    __shared__ int   slast;

    const int b   = blockIdx.x;
    const int tid = threadIdx.x;
    const float* pred = outbuf + 1 + NROWS;

    {   // exp(emissions) for this batch, padded [L][8] (col 7 = 0)
        const float* pb = pred + (size_t)b * L_ * NT;
        for (int i = tid; i < L_ * NT; i += 128) {
            int r = i / NT, c = i % NT;
            sEE[r * 8 + c] = __expf(pb[i]);
        }
        for (int r = tid; r < L_; r += 128) sEE[r * 8 + 7] = 0.f;
    }
    if (tid < 64) {
        int n = tid >> 3, p = tid & 7;
        sET[n][p] = (n < NT && p < NT) ? __expf(trans[n * NT + p]) : 0.f;
    }
    if (tid < 49) sT[tid] = trans[tid];
    __syncthreads();

    // ---- Stage A: per-chunk matrix product (thread per column) ----
    {
        const int chunk = tid >> 3;     // 0..15
        const int col   = tid & 7;      // 0..7 (7 = zero pad column)
        float ET[NT][NT];
        #pragma unroll
        for (int n = 0; n < NT; n++)
            #pragma unroll
            for (int p = 0; p < NT; p++) ET[n][p] = sET[n][p];

        const int t0 = chunk * 32;
        float u[NT];
        #pragma unroll
        for (int n = 0; n < NT; n++)
            u[n] = (col < NT) ? sET[n][col] * sEE[t0 * 8 + n] : 0.f;
        float s = 0.f;

        for (int step = 1; step < 32; step++) {
            const float* ee = &sEE[(t0 + step) * 8];
            float v[NT];
            #pragma unroll
            for (int n = 0; n < NT; n++) {
                float a = ET[n][0] * u[0];
                #pragma unroll
                for (int p = 1; p < NT; p++) a = fmaf(ET[n][p], u[p], a);
                v[n] = a * ee[n];
            }
            #pragma unroll
            for (int n = 0; n < NT; n++) u[n] = v[n];

            if ((step & 7) == 7) {      // renormalize (shared scale per chunk)
                float m = u[0];
                #pragma unroll
                for (int n = 1; n < NT; n++) m = fmaxf(m, u[n]);
                m = fmaxf(m, __shfl_xor_sync(0xffffffffu, m, 1));
                m = fmaxf(m, __shfl_xor_sync(0xffffffffu, m, 2));
                m = fmaxf(m, __shfl_xor_sync(0xffffffffu, m, 4));
                if (m > 0.f) {
                    float inv = __frcp_rn(m);
                    #pragma unroll
                    for (int n = 0; n < NT; n++) u[n] *= inv;
                    s += __logf(m);
                }
            }
        }
        // final state renormalized to max=1 (renorm hit step 31)
        #pragma unroll
        for (int n = 0; n < NT; n++) sM[chunk][col][n] = u[n];
        sM[chunk][col][7] = 0.f;
        if (col == 0) sS[chunk] = s;
    }
    __syncthreads();

    // ---- Stage B: sequential matrix-vector combine (warp 0, lanes 0..7),
    //      renorm only every 4th combine (entries in [0,1], growth <= 7^4).
    //      Gold score in parallel on warp 1. ----
    if (tid < 8) {
        const int n = tid;
        float v     = sM[0][START_][n];   // init vector = e_START
        float scale = sS[0];
        for (int c = 1; c < 16; c++) {
            sv[n] = v;
            __syncwarp(0x000000ffu);
            float a = 0.f;
            #pragma unroll
            for (int j = 0; j < NT; j++) a = fmaf(sM[c][j][n], sv[j], a);
            v = a;
            scale += sS[c];
            if ((c & 3) == 3) {          // sparse renormalization
                float m = v;
                m = fmaxf(m, __shfl_xor_sync(0xffu, m, 1));
                m = fmaxf(m, __shfl_xor_sync(0xffu, m, 2));
                m = fmaxf(m, __shfl_xor_sync(0xffu, m, 4));
                if (m > 0.f) { v *= __frcp_rn(m); scale += __logf(m); }
            }
            __syncwarp(0x000000ffu);
        }
        sv[n] = v;
        if (n == 0) svscale = scale;
    } else if (tid >= 32 && tid < 64) {
        const int lane = tid - 32;
        const int base = b * L_;
        float acc = 0.f;
        #pragma unroll 4
        for (int k = 0; k < 16; k++) {
            int t   = lane + k * 32;
            int tag = labels[base + t];
            int pt  = (t == 0) ? START_ : labels[base + t - 1];
            acc += pred[(size_t)(base + t) * NT + tag] + sT[tag * NT + pt];
        }
        #pragma unroll
        for (int o = 16; o > 0; o >>= 1)
            acc += __shfl_xor_sync(0xffffffffu, acc, o);
        if (lane == 0) sgold = acc + sT[STOP_ * NT + labels[base + L_ - 1]];
    }
    __syncthreads();

    if (tid == 0) {
        float sum = 0.f;
        #pragma unroll
        for (int n = 0; n < NT; n++) sum += sv[n] * sET[STOP_][n];
        g_nll[b] = __logf(sum) + svscale - sgold;
        __threadfence();
        slast = (atomicAdd(&g_cnt, 1) == B_ - 1);
    }
    __syncthreads();

    // Last block: deterministic tid-ordered sum of all 64 NLLs -> out[0]
    if (slast) {
        __shared__ float sred[64];
        __threadfence();
        if (tid < 64) sred[tid] = *((volatile float*)&g_nll[tid]);
        __syncthreads();
        if (tid < 32) sred[tid] += sred[tid + 32];
        __syncthreads();
        if (tid == 0) {
            float s = 0.f;
            #pragma unroll
            for (int i = 0; i < 32; i++) s += sred[i];
            outbuf[0] = s;
            g_cnt = 0;          // reset for next graph replay
        }
    }
}

extern "C" void kernel_launch(void* const* d_in, const int* in_sizes, int n_in,
                              void* d_out, int out_size)
{
    const float* X      = (const float*)d_in[0];
    const int*   labels = (const int*)  d_in[1];
    const float* W      = (const float*)d_in[2];
    const float* bias   = (const float*)d_in[3];
    const float* trans  = (const float*)d_in[4];
    float* out = (float*)d_out;

    static int smem_cfg = 0;
    if (!smem_cfg) {
        cudaFuncSetAttribute(k1_gemm,
                             cudaFuncAttributeMaxDynamicSharedMemorySize,
                             SMEM_BYTES);
        smem_cfg = 1;
    }

    k1_gemm<<<NROWS / RPB, TPB, SMEM_BYTES>>>(X, labels, W, bias, out);
    k2_crf<<<B_, 128>>>(trans, labels, out);
}

// round 11
// speedup vs baseline: 1.9675x; 1.0081x over previous
#include <cuda_runtime.h>
#include <math.h>

// Problem constants
#define B_    64
#define L_    512
#define C_    1024
#define NT    7
#define START_ 5
#define STOP_  6
#define NROWS (B_ * L_)   // 32768

// k1 tiling: 128 rows/block (4 warps x 32 rows), 32-col tiles,
// 4-deep PER-WARP cp.async ring (no block barriers in the mainloop).
#define RPB   128
#define TPB   128
#define KC    32
#define NTILE (C_ / KC)           // 32
#define NSTG  4
#define PADW  36                  // padded floats per smem row (conflict-free)
#define WSTG_BYTES (32 * PADW * 4)               // 4608 per warp-stage
#define SW_OFF     (4 * NSTG * WSTG_BYTES)       // 73728 (4 warps)
#define SW_BYTES   (NT * (C_ / 2) * 8)           // 28672
#define SB_OFF     (SW_OFF + SW_BYTES)
#define SMEM_BYTES (SB_OFF + 64)                 // ~102.5 KB -> 2 blocks/SM

// k2: 32 chunks x 16 steps, 256 threads
#define NCHK  32
#define CLEN  16

__device__ float g_nll[B_];
__device__ int   g_cnt;          // zero-init; self-resetting each run

// packed f32x2 FMA (Blackwell; PTX-only form -> single FFMA2)
__device__ __forceinline__ void ffma2(unsigned long long& d,
                                      unsigned long long a,
                                      unsigned long long b) {
    asm("fma.rn.f32x2 %0, %1, %2, %0;" : "+l"(d) : "l"(a), "l"(b));
}
__device__ __forceinline__ void lds_v2b64(unsigned smem_addr,
                                          unsigned long long& lo,
                                          unsigned long long& hi) {
    asm volatile("ld.shared.v2.b64 {%0, %1}, [%2];"
                 : "=l"(lo), "=l"(hi) : "r"(smem_addr));
}
__device__ __forceinline__ float unpack_sum(unsigned long long v) {
    union { unsigned long long u; float2 f; } cv; cv.u = v;
    return cv.f.x + cv.f.y;
}
__device__ __forceinline__ unsigned smem_u32(const void* p) {
    unsigned a;
    asm("{ .reg .u64 t; cvta.to.shared.u64 t, %1; cvt.u32.u64 %0, t; }"
        : "=r"(a) : "l"(p));
    return a;
}
__device__ __forceinline__ void cp_async16(unsigned dst, const void* src) {
    asm volatile("cp.async.cg.shared.global [%0], [%1], 16;"
                 :: "r"(dst), "l"(src));
}
__device__ __forceinline__ void cp_commit() {
    asm volatile("cp.async.commit_group;");
}
template <int N>
__device__ __forceinline__ void cp_wait() {
    asm volatile("cp.async.wait_group %0;" :: "n"(N));
}

// ---------------------------------------------------------------------------
// Kernel 1: pred = X @ W^T + b.  Thread-per-row; each WARP owns a private
// 4-deep cp.async pipeline over its 32 rows -> no block barriers, warps
// stream memory continuously. W broadcast from shared, f32x2 FMAs.
// ---------------------------------------------------------------------------
__global__ void __launch_bounds__(TPB) k1_gemm(
    const float* __restrict__ X, const int* __restrict__ labels,
    const float* __restrict__ W, const float* __restrict__ bias,
    float* __restrict__ out)
{
    extern __shared__ __align__(16) char dsm[];
    unsigned long long* sW2 = (unsigned long long*)(dsm + SW_OFF); // [NT][C_/2]
    float* sb = (float*)(dsm + SB_OFF);
    const unsigned sx_base = smem_u32(dsm);

    const int tid  = threadIdx.x;
    const int wid  = tid >> 5;
    const int lane = tid & 31;

    for (int i = tid; i < NT * (C_ / 2); i += TPB)
        sW2[i] = ((const unsigned long long*)W)[i];
    if (tid < NT) sb[tid] = bias[tid];
    __syncthreads();

    const int wrow0 = blockIdx.x * RPB + wid * 32;
    const float* xw = X + (size_t)wrow0 * C_;
    const unsigned wbase = sx_base + wid * (NSTG * WSTG_BYTES);

    #define LOAD_TILE(T, BUF) do {                                          \
        const float* sbse = xw + (T) * KC;                                  \
        unsigned dbse = wbase + (BUF) * WSTG_BYTES;                         \
        _Pragma("unroll")                                                   \
        for (int i_ = 0; i_ < 8; i_++) {                                    \
            int seg_ = i_ * 32 + lane;                                      \
            int r_ = seg_ >> 3, j_ = seg_ & 7;                              \
            cp_async16(dbse + r_ * (PADW * 4) + j_ * 16,                    \
                       sbse + (size_t)r_ * C_ + j_ * 4);                    \
        }                                                                   \
    } while (0)

    LOAD_TILE(0, 0); cp_commit();
    LOAD_TILE(1, 1); cp_commit();
    LOAD_TILE(2, 2); cp_commit();

    unsigned long long acc[NT];
    #pragma unroll
    for (int g = 0; g < NT; g++) acc[g] = 0ull;

    for (int t = 0; t < NTILE; t++) {
        if (t + 3 < NTILE) {
            LOAD_TILE(t + 3, (t + 3) & (NSTG - 1));
            cp_commit();
            cp_wait<3>();
        } else {
            cp_wait<0>();
        }
        __syncwarp();

        const unsigned rbase = wbase + (t & (NSTG - 1)) * WSTG_BYTES
                             + lane * (PADW * 4);
        const unsigned long long* wrow = sW2 + t * (KC / 2);
        #pragma unroll
        for (int j = 0; j < 8; j++) {
            unsigned long long xlo, xhi;
            lds_v2b64(rbase + j * 16, xlo, xhi);
            #pragma unroll
            for (int g = 0; g < NT; g++) {
                ffma2(acc[g], xlo, wrow[(size_t)g * (C_ / 2) + j * 2]);
                ffma2(acc[g], xhi, wrow[(size_t)g * (C_ / 2) + j * 2 + 1]);
            }
        }
        __syncwarp();
    }

    const int grow = wrow0 + lane;
    float* pred = out + 1 + NROWS;
    #pragma unroll
    for (int g = 0; g < NT; g++)
        pred[(size_t)grow * NT + g] = unpack_sum(acc[g]) + sb[g];
    out[1 + grow] = (float)labels[grow];
    #undef LOAD_TILE
}

// ---------------------------------------------------------------------------
// Kernel 2: CRF forward, restructured for parallelism:
//   256 threads; 32 chunks x 16 steps (half the serial depth, 2 warps/SMSP);
//   binary-tree matrix-product combine (5 parallel levels, no serial scan);
//   gold score across all 256 threads; fused final reduction.
// ---------------------------------------------------------------------------
__global__ void __launch_bounds__(256) k2_crf(
    const float* __restrict__ trans,
    const int* __restrict__ labels,
    float* __restrict__ outbuf)
{
    __shared__ float sEE[L_ * 8];          // 16 KB exp-emissions
    __shared__ float sET[8][8];            // exp(transitions)
    __shared__ float sT[49];               // raw transitions
    __shared__ float sMa[NCHK][8][8];      // chunk matrices [c][col][row], 8 KB
    __shared__ float sMb[NCHK / 2][8][8];  // tree ping-pong, 4 KB
    __shared__ float sS[NCHK];             // chunk log-scales
    __shared__ float sgred[8];
    __shared__ float svscale, sgold;
    __shared__ int   slast;

    const int b   = blockIdx.x;
    const int tid = threadIdx.x;
    const float* pred = outbuf + 1 + NROWS;

    {   // exp(emissions), padded [L][8] (col 7 = 0)
        const float* pb = pred + (size_t)b * L_ * NT;
        for (int i = tid; i < L_ * NT; i += 256) {
            int r = i / NT, c = i % NT;
            sEE[r * 8 + c] = __expf(pb[i]);
        }
        for (int r = tid; r < L_; r += 256) sEE[r * 8 + 7] = 0.f;
    }
    if (tid < 64) {
        int n = tid >> 3, p = tid & 7;
        sET[n][p] = (n < NT && p < NT) ? __expf(trans[n * NT + p]) : 0.f;
    }
    if (tid < 49) sT[tid] = trans[tid];
    __syncthreads();

    // ---- Stage A: per-chunk (16-step) matrix product, thread per column ----
    {
        const int chunk = tid >> 3;     // 0..31
        const int col   = tid & 7;      // 0..7 (7 = zero pad column)
        float ET[NT][NT];
        #pragma unroll
        for (int n = 0; n < NT; n++)
            #pragma unroll
            for (int p = 0; p < NT; p++) ET[n][p] = sET[n][p];

        const int t0 = chunk * CLEN;
        float u[NT];
        #pragma unroll
        for (int n = 0; n < NT; n++)
            u[n] = (col < NT) ? sET[n][col] * sEE[t0 * 8 + n] : 0.f;
        float s = 0.f;

        #pragma unroll 4
        for (int step = 1; step < CLEN; step++) {
            const float* ee = &sEE[(t0 + step) * 8];
            float v[NT];
            #pragma unroll
            for (int n = 0; n < NT; n++) {
                float a = ET[n][0] * u[0];
                #pragma unroll
                for (int p = 1; p < NT; p++) a = fmaf(ET[n][p], u[p], a);
                v[n] = a * ee[n];
            }
            #pragma unroll
            for (int n = 0; n < NT; n++) u[n] = v[n];

            if ((step & 7) == 7) {      // renorm at steps 7, 15
                float m = u[0];
                #pragma unroll
                for (int n = 1; n < NT; n++) m = fmaxf(m, u[n]);
                m = fmaxf(m, __shfl_xor_sync(0xffffffffu, m, 1));
                m = fmaxf(m, __shfl_xor_sync(0xffffffffu, m, 2));
                m = fmaxf(m, __shfl_xor_sync(0xffffffffu, m, 4));
                if (m > 0.f) {
                    float inv = __frcp_rn(m);
                    #pragma unroll
                    for (int n = 0; n < NT; n++) u[n] *= inv;
                    s += __logf(m);
                }
            }
        }
        #pragma unroll
        for (int n = 0; n < NT; n++) sMa[chunk][col][n] = u[n];
        sMa[chunk][col][7] = 0.f;
        if (col == 0) sS[chunk] = s;
    }
    __syncthreads();

    // Total scale = sum of chunk scales (no in-tree renorm needed:
    // matrices are max<=1 normalized; growth across 5 levels <= 7^5).
    if (tid < 32) {
        float s = sS[tid];
        #pragma unroll
        for (int o = 16; o > 0; o >>= 1)
            s += __shfl_xor_sync(0xffffffffu, s, o);
        if (tid == 0) svscale = s;
    }

    // ---- Gold score over all 256 threads (2 tokens each) ----
    {
        const int base = b * L_;
        float acc = 0.f;
        #pragma unroll
        for (int k = 0; k < 2; k++) {
            int t   = tid + k * 256;
            int tag = labels[base + t];
            int pt  = (t == 0) ? START_ : labels[base + t - 1];
            acc += pred[(size_t)(base + t) * NT + tag] + sT[tag * NT + pt];
        }
        #pragma unroll
        for (int o = 16; o > 0; o >>= 1)
            acc += __shfl_xor_sync(0xffffffffu, acc, o);
        if ((tid & 31) == 0) sgred[tid >> 5] = acc;
    }
    __syncthreads();
    if (tid == 0) {
        float g = 0.f;
        #pragma unroll
        for (int i = 0; i < 8; i++) g += sgred[i];
        sgold = g + sT[STOP_ * NT + labels[b * L_ + L_ - 1]];
    }

    // ---- Tree combine: 5 levels of parallel 8x8 matrix products ----
    // dst[k][col][row] = sum_j srcB=src[2k+1][j][row] * srcA=src[2k][col][j]
    #define TREE_LEVEL(SRC, DST, NPAIR) do {                                \
        for (int idx = tid; idx < (NPAIR) * 64; idx += 256) {               \
            int k_ = idx >> 6, e_ = idx & 63;                               \
            int col_ = e_ >> 3, row_ = e_ & 7;                              \
            const float* A_ = &SRC[2 * k_][col_][0];                        \
            const float* Bv = &SRC[2 * k_ + 1][0][row_];                    \
            float a_ = Bv[0] * A_[0];                                       \
            _Pragma("unroll")                                               \
            for (int j_ = 1; j_ < 8; j_++)                                  \
                a_ = fmaf(Bv[j_ * 8], A_[j_], a_);                          \
            DST[k_][col_][row_] = a_;                                       \
        }                                                                   \
        __syncthreads();                                                    \
    } while (0)

    TREE_LEVEL(sMa, sMb, 16);   // 32 -> 16
    TREE_LEVEL(sMb, sMa, 8);    // 16 -> 8
    TREE_LEVEL(sMa, sMb, 4);    // 8  -> 4
    TREE_LEVEL(sMb, sMa, 2);    // 4  -> 2
    TREE_LEVEL(sMa, sMb, 1);    // 2  -> 1  (total product in sMb[0])
    #undef TREE_LEVEL

    if (tid == 0) {
        float sum = 0.f;
        #pragma unroll
        for (int n = 0; n < NT; n++)
            sum += sMb[0][START_][n] * sET[STOP_][n];
        g_nll[b] = __logf(sum) + svscale - sgold;
        __threadfence();
        slast = (atomicAdd(&g_cnt, 1) == B_ - 1);
    }
    __syncthreads();

    // Last block: deterministic sum of all 64 NLLs -> out[0]
    if (slast) {
        __shared__ float sred[64];
        __threadfence();
        if (tid < 64) sred[tid] = *((volatile float*)&g_nll[tid]);
        __syncthreads();
        if (tid < 32) sred[tid] += sred[tid + 32];
        __syncthreads();
        if (tid == 0) {
            float s = 0.f;
            #pragma unroll
            for (int i = 0; i < 32; i++) s += sred[i];
            outbuf[0] = s;
            g_cnt = 0;          // reset for next graph replay
        }
    }
}

extern "C" void kernel_launch(void* const* d_in, const int* in_sizes, int n_in,
                              void* d_out, int out_size)
{
    const float* X      = (const float*)d_in[0];
    const int*   labels = (const int*)  d_in[1];
    const float* W      = (const float*)d_in[2];
    const float* bias   = (const float*)d_in[3];
    const float* trans  = (const float*)d_in[4];
    float* out = (float*)d_out;

    static int smem_cfg = 0;
    if (!smem_cfg) {
        cudaFuncSetAttribute(k1_gemm,
                             cudaFuncAttributeMaxDynamicSharedMemorySize,
                             SMEM_BYTES);
        smem_cfg = 1;
    }

    k1_gemm<<<NROWS / RPB, TPB, SMEM_BYTES>>>(X, labels, W, bias, out);
    k2_crf<<<B_, 256>>>(trans, labels, out);
}

// round 13
// speedup vs baseline: 2.1228x; 1.0789x over previous
#include <cuda_runtime.h>
#include <math.h>

// Problem constants
#define B_    64
#define L_    512
#define C_    1024
#define NT    7
#define START_ 5
#define STOP_  6
#define NROWS (B_ * L_)   // 32768

// k1 tiling: 128 rows/block (4 warps x 32 rows), 32-col tiles,
// 4-deep PER-WARP cp.async ring (no block barriers in the mainloop).
#define RPB   128
#define TPB   128
#define KC    32
#define NTILE (C_ / KC)           // 32
#define NSTG  4
#define PADW  36                  // padded floats per smem row (conflict-free)
#define WSTG_BYTES (32 * PADW * 4)               // 4608 per warp-stage
#define SW_OFF     (4 * NSTG * WSTG_BYTES)       // 73728 (4 warps)
#define SW_BYTES   (NT * (C_ / 2) * 8)           // 28672
#define SB_OFF     (SW_OFF + SW_BYTES)
#define SMEM_BYTES (SB_OFF + 64)                 // ~102.5 KB -> 2 blocks/SM

// k2: 32 chunks x 16 steps, 256 threads
#define NCHK  32
#define CLEN  16
#define NFILL (L_ * NT / 256)     // 14 pred elements per thread

__device__ float g_nll[B_];
__device__ int   g_cnt;          // zero-init; self-resetting each run

// packed f32x2 FMA (Blackwell; PTX-only form -> single FFMA2)
__device__ __forceinline__ void ffma2(unsigned long long& d,
                                      unsigned long long a,
                                      unsigned long long b) {
    asm("fma.rn.f32x2 %0, %1, %2, %0;" : "+l"(d) : "l"(a), "l"(b));
}
__device__ __forceinline__ void lds_v2b64(unsigned smem_addr,
                                          unsigned long long& lo,
                                          unsigned long long& hi) {
    asm volatile("ld.shared.v2.b64 {%0, %1}, [%2];"
                 : "=l"(lo), "=l"(hi) : "r"(smem_addr));
}
__device__ __forceinline__ float unpack_sum(unsigned long long v) {
    union { unsigned long long u; float2 f; } cv; cv.u = v;
    return cv.f.x + cv.f.y;
}
__device__ __forceinline__ unsigned smem_u32(const void* p) {
    unsigned a;
    asm("{ .reg .u64 t; cvta.to.shared.u64 t, %1; cvt.u32.u64 %0, t; }"
        : "=r"(a) : "l"(p));
    return a;
}
__device__ __forceinline__ void cp_async16(unsigned dst, const void* src) {
    asm volatile("cp.async.cg.shared.global [%0], [%1], 16;"
                 :: "r"(dst), "l"(src));
}
__device__ __forceinline__ void cp_commit() {
    asm volatile("cp.async.commit_group;");
}
template <int N>
__device__ __forceinline__ void cp_wait() {
    asm volatile("cp.async.wait_group %0;" :: "n"(N));
}

// ---------------------------------------------------------------------------
// Kernel 1: pred = X @ W^T + b.  Thread-per-row; each WARP owns a private
// 4-deep cp.async pipeline over its 32 rows -> no block barriers, warps
// stream memory continuously. W broadcast from shared, f32x2 FMAs.
// ---------------------------------------------------------------------------
__global__ void __launch_bounds__(TPB) k1_gemm(
    const float* __restrict__ X, const int* __restrict__ labels,
    const float* __restrict__ W, const float* __restrict__ bias,
    float* __restrict__ out)
{
    extern __shared__ __align__(16) char dsm[];
    unsigned long long* sW2 = (unsigned long long*)(dsm + SW_OFF); // [NT][C_/2]
    float* sb = (float*)(dsm + SB_OFF);
    const unsigned sx_base = smem_u32(dsm);

    const int tid  = threadIdx.x;
    const int wid  = tid >> 5;
    const int lane = tid & 31;

    for (int i = tid; i < NT * (C_ / 2); i += TPB)
        sW2[i] = ((const unsigned long long*)W)[i];
    if (tid < NT) sb[tid] = bias[tid];
    __syncthreads();

    const int wrow0 = blockIdx.x * RPB + wid * 32;
    const float* xw = X + (size_t)wrow0 * C_;
    const unsigned wbase = sx_base + wid * (NSTG * WSTG_BYTES);

    #define LOAD_TILE(T, BUF) do {                                          \
        const float* sbse = xw + (T) * KC;                                  \
        unsigned dbse = wbase + (BUF) * WSTG_BYTES;                         \
        _Pragma("unroll")                                                   \
        for (int i_ = 0; i_ < 8; i_++) {                                    \
            int seg_ = i_ * 32 + lane;                                      \
            int r_ = seg_ >> 3, j_ = seg_ & 7;                              \
            cp_async16(dbse + r_ * (PADW * 4) + j_ * 16,                    \
                       sbse + (size_t)r_ * C_ + j_ * 4);                    \
        }                                                                   \
    } while (0)

    LOAD_TILE(0, 0); cp_commit();
    LOAD_TILE(1, 1); cp_commit();
    LOAD_TILE(2, 2); cp_commit();

    unsigned long long acc[NT];
    #pragma unroll
    for (int g = 0; g < NT; g++) acc[g] = 0ull;

    for (int t = 0; t < NTILE; t++) {
        if (t + 3 < NTILE) {
            LOAD_TILE(t + 3, (t + 3) & (NSTG - 1));
            cp_commit();
            cp_wait<3>();
        } else {
            cp_wait<0>();
        }
        __syncwarp();

        const unsigned rbase = wbase + (t & (NSTG - 1)) * WSTG_BYTES
                             + lane * (PADW * 4);
        const unsigned long long* wrow = sW2 + t * (KC / 2);
        #pragma unroll
        for (int j = 0; j < 8; j++) {
            unsigned long long xlo, xhi;
            lds_v2b64(rbase + j * 16, xlo, xhi);
            #pragma unroll
            for (int g = 0; g < NT; g++) {
                ffma2(acc[g], xlo, wrow[(size_t)g * (C_ / 2) + j * 2]);
                ffma2(acc[g], xhi, wrow[(size_t)g * (C_ / 2) + j * 2 + 1]);
            }
        }
        __syncwarp();
    }

    const int grow = wrow0 + lane;
    float* pred = out + 1 + NROWS;
    #pragma unroll
    for (int g = 0; g < NT; g++)
        pred[(size_t)grow * NT + g] = unpack_sum(acc[g]) + sb[g];
    out[1 + grow] = (float)labels[grow];
    #undef LOAD_TILE
}

// ---------------------------------------------------------------------------
// Kernel 2: CRF forward.  MLP-batched fill (14 independent LDGs per thread
// before any expf), labels staged in shared, then 32x16 chunked matrix
// products + binary-tree combine + gold + fused final reduction.
// ---------------------------------------------------------------------------
__global__ void __launch_bounds__(256) k2_crf(
    const float* __restrict__ trans,
    const int* __restrict__ labels,
    float* __restrict__ outbuf)
{
    __shared__ float sEE[L_ * 8];          // 16 KB exp-emissions
    __shared__ float sET[8][8];            // exp(transitions)
    __shared__ float sT[49];               // raw transitions
    __shared__ int   sLab[L_];             // labels for this batch (2 KB)
    __shared__ float sMa[NCHK][8][8];      // chunk matrices [c][col][row]
    __shared__ float sMb[NCHK / 2][8][8];  // tree ping-pong
    __shared__ float sS[NCHK];             // chunk log-scales
    __shared__ float sgred[8];
    __shared__ float svscale, sgold;
    __shared__ int   slast;

    const int b   = blockIdx.x;
    const int tid = threadIdx.x;
    const int base = b * L_;
    const float* pred = outbuf + 1 + NROWS;
    const float* pb = pred + (size_t)b * L_ * NT;

    // ---- Phase 0: batched independent loads (MLP = 16) ----
    float xv[NFILL];
    #pragma unroll
    for (int k = 0; k < NFILL; k++) xv[k] = pb[tid + k * 256];
    const int lv0 = labels[base + tid];
    const int lv1 = labels[base + tid + 256];

    // expf + shared stores (loads already in flight / landed)
    #pragma unroll
    for (int k = 0; k < NFILL; k++) {
        const int i = tid + k * 256;
        sEE[(i / NT) * 8 + (i % NT)] = __expf(xv[k]);
    }
    {
        #pragma unroll
        for (int k = 0; k < 2; k++) {
            const int r = tid + k * 256;
            sEE[r * 8 + 7] = 0.f;
        }
    }
    sLab[tid] = lv0;
    sLab[tid + 256] = lv1;
    if (tid < 64) {
        int n = tid >> 3, p = tid & 7;
        sET[n][p] = (n < NT && p < NT) ? __expf(trans[n * NT + p]) : 0.f;
    }
    if (tid < 49) sT[tid] = trans[tid];
    __syncthreads();

    // ---- Stage A: per-chunk (16-step) matrix product, thread per column ----
    {
        const int chunk = tid >> 3;     // 0..31
        const int col   = tid & 7;      // 0..7 (7 = zero pad column)
        float ET[NT][NT];
        #pragma unroll
        for (int n = 0; n < NT; n++)
            #pragma unroll
            for (int p = 0; p < NT; p++) ET[n][p] = sET[n][p];

        const int t0 = chunk * CLEN;
        float u[NT];
        #pragma unroll
        for (int n = 0; n < NT; n++)
            u[n] = (col < NT) ? sET[n][col] * sEE[t0 * 8 + n] : 0.f;
        float s = 0.f;

        #pragma unroll 4
        for (int step = 1; step < CLEN; step++) {
            const float* ee = &sEE[(t0 + step) * 8];
            float v[NT];
            #pragma unroll
            for (int n = 0; n < NT; n++) {
                float a = ET[n][0] * u[0];
                #pragma unroll
                for (int p = 1; p < NT; p++) a = fmaf(ET[n][p], u[p], a);
                v[n] = a * ee[n];
            }
            #pragma unroll
            for (int n = 0; n < NT; n++) u[n] = v[n];

            if ((step & 7) == 7) {      // renorm at steps 7, 15
                float m = u[0];
                #pragma unroll
                for (int n = 1; n < NT; n++) m = fmaxf(m, u[n]);
                m = fmaxf(m, __shfl_xor_sync(0xffffffffu, m, 1));
                m = fmaxf(m, __shfl_xor_sync(0xffffffffu, m, 2));
                m = fmaxf(m, __shfl_xor_sync(0xffffffffu, m, 4));
                if (m > 0.f) {
                    float inv = __frcp_rn(m);
                    #pragma unroll
                    for (int n = 0; n < NT; n++) u[n] *= inv;
                    s += __logf(m);
                }
            }
        }
        #pragma unroll
        for (int n = 0; n < NT; n++) sMa[chunk][col][n] = u[n];
        sMa[chunk][col][7] = 0.f;
        if (col == 0) sS[chunk] = s;
    }

    // ---- Gold score (tags from shared; pred loads hit L1 from Phase 0) ----
    {
        float acc = 0.f;
        #pragma unroll
        for (int k = 0; k < 2; k++) {
            const int t   = tid + k * 256;
            const int tag = sLab[t];
            const int pt  = (t == 0) ? START_ : sLab[t - 1];
            acc += pb[(size_t)t * NT + tag] + sT[tag * NT + pt];
        }
        #pragma unroll
        for (int o = 16; o > 0; o >>= 1)
            acc += __shfl_xor_sync(0xffffffffu, acc, o);
        if ((tid & 31) == 0) sgred[tid >> 5] = acc;
    }
    __syncthreads();

    // Total scale = sum of chunk scales; gold total
    if (tid == 0) {
        float g = 0.f;
        #pragma unroll
        for (int i = 0; i < 8; i++) g += sgred[i];
        sgold = g + sT[STOP_ * NT + sLab[L_ - 1]];
        float s = 0.f;
        #pragma unroll
        for (int i = 0; i < NCHK; i++) s += sS[i];
        svscale = s;
    }

    // ---- Tree combine: 5 levels of parallel 8x8 matrix products ----
    #define TREE_LEVEL(SRC, DST, NPAIR) do {                                \
        for (int idx = tid; idx < (NPAIR) * 64; idx += 256) {               \
            int k_ = idx >> 6, e_ = idx & 63;                               \
            int col_ = e_ >> 3, row_ = e_ & 7;                              \
            const float* A_ = &SRC[2 * k_][col_][0];                        \
            const float* Bv = &SRC[2 * k_ + 1][0][row_];                    \
            float a_ = Bv[0] * A_[0];                                       \
            _Pragma("unroll")                                               \
            for (int j_ = 1; j_ < 8; j_++)                                  \
                a_ = fmaf(Bv[j_ * 8], A_[j_], a_);                          \
            DST[k_][col_][row_] = a_;                                       \
        }                                                                   \
        __syncthreads();                                                    \
    } while (0)

    TREE_LEVEL(sMa, sMb, 16);   // 32 -> 16
    TREE_LEVEL(sMb, sMa, 8);    // 16 -> 8
    TREE_LEVEL(sMa, sMb, 4);    // 8  -> 4
    TREE_LEVEL(sMb, sMa, 2);    // 4  -> 2
    TREE_LEVEL(sMa, sMb, 1);    // 2  -> 1  (total product in sMb[0])
    #undef TREE_LEVEL

    if (tid == 0) {
        float sum = 0.f;
        #pragma unroll
        for (int n = 0; n < NT; n++)
            sum += sMb[0][START_][n] * sET[STOP_][n];
        g_nll[b] = __logf(sum) + svscale - sgold;
        __threadfence();
        slast = (atomicAdd(&g_cnt, 1) == B_ - 1);
    }
    __syncthreads();

    // Last block: deterministic sum of all 64 NLLs -> out[0]
    if (slast) {
        __shared__ float sred[64];
        __threadfence();
        if (tid < 64) sred[tid] = *((volatile float*)&g_nll[tid]);
        __syncthreads();
        if (tid < 32) sred[tid] += sred[tid + 32];
        __syncthreads();
        if (tid == 0) {
            float s = 0.f;
            #pragma unroll
            for (int i = 0; i < 32; i++) s += sred[i];
            outbuf[0] = s;
            g_cnt = 0;          // reset for next graph replay
        }
    }
}

extern "C" void kernel_launch(void* const* d_in, const int* in_sizes, int n_in,
                              void* d_out, int out_size)
{
    const float* X      = (const float*)d_in[0];
    const int*   labels = (const int*)  d_in[1];
    const float* W      = (const float*)d_in[2];
    const float* bias   = (const float*)d_in[3];
    const float* trans  = (const float*)d_in[4];
    float* out = (float*)d_out;

    static int smem_cfg = 0;
    if (!smem_cfg) {
        cudaFuncSetAttribute(k1_gemm,
                             cudaFuncAttributeMaxDynamicSharedMemorySize,
                             SMEM_BYTES);
        smem_cfg = 1;
    }

    k1_gemm<<<NROWS / RPB, TPB, SMEM_BYTES>>>(X, labels, W, bias, out);
    k2_crf<<<B_, 256>>>(trans, labels, out);
}